// round 8
// baseline (speedup 1.0000x reference)
#include <cuda_runtime.h>
#include <cuda_bf16.h>
#include <cstdint>

// Problem constants
static constexpr int T_ = 2048;
static constexpr int B_ = 16;
static constexpr int D_ = 1024;
static constexpr int M_ = T_ * B_;    // 32768
static constexpr int N_ = 3 * D_;     // 3072
static constexpr int K_ = D_;         // 1024
static constexpr int K3_ = 3 * K_;    // 3072 packed split-K
static constexpr float EPS_ = 1e-5f;

// GEMM tiling (mma.sync path — tcgen05 unavailable: harness emits compute_103 PTX)
static constexpr int BM = 128;
static constexpr int BN = 256;
static constexpr int BK = 64;
static constexpr int KT = K3_ / BK;       // 48 K-steps
static constexpr int STAGES = 3;
static constexpr int APAD = 8, BPAD = 8;
static constexpr int A_BYTES = BM * (BK + APAD) * 2;   // 18432
static constexpr int B_BYTES = BK * (BN + BPAD) * 2;   // 33792
static constexpr int STAGE_BYTES = A_BYTES + B_BYTES;  // 52224
static constexpr int DSMEM_BYTES = STAGES * STAGE_BYTES; // 156672

// Scratch (__device__ globals; no runtime allocation allowed)
__device__ __nv_bfloat16 g_A2[(size_t)M_ * K3_];   // rows x [hi | hi | lo]
__device__ __nv_bfloat16 g_B2[(size_t)K3_ * N_];   // K'-major x N: [Whi | Wlo | Whi]
__device__ float g_pre[(size_t)M_ * N_];
__device__ float2 g_stats[M_];                     // per-row (mu, rsig)

// ---------------------------------------------------------------------------
// PTX helpers
// ---------------------------------------------------------------------------
#define CP_ASYNC16(dst, src) \
    asm volatile("cp.async.cg.shared.global [%0], [%1], 16;\n" :: "r"(dst), "l"(src))
#define CP_COMMIT() asm volatile("cp.async.commit_group;\n" ::)
#define CP_WAIT(n)  asm volatile("cp.async.wait_group %0;\n" :: "n"(n))

#define LDSM4(R0, R1, R2, R3, addr)                                                \
    asm volatile("ldmatrix.sync.aligned.m8n8.x4.shared.b16 {%0,%1,%2,%3}, [%4];\n" \
                 : "=r"(R0), "=r"(R1), "=r"(R2), "=r"(R3) : "r"(addr))
#define LDSM4T(R0, R1, R2, R3, addr)                                               \
    asm volatile("ldmatrix.sync.aligned.m8n8.x4.trans.shared.b16 {%0,%1,%2,%3}, [%4];\n" \
                 : "=r"(R0), "=r"(R1), "=r"(R2), "=r"(R3) : "r"(addr))
#define MMA16816(C, A0, A1, A2r, A3, B0, B1)                                 \
    asm volatile("mma.sync.aligned.m16n8k16.row.col.f32.bf16.bf16.f32 "      \
                 "{%0,%1,%2,%3},{%4,%5,%6,%7},{%8,%9},{%0,%1,%2,%3};\n"      \
                 : "+f"(C[0]), "+f"(C[1]), "+f"(C[2]), "+f"(C[3])            \
                 : "r"(A0), "r"(A1), "r"(A2r), "r"(A3), "r"(B0), "r"(B1))

// ---------------------------------------------------------------------------
// Kernel 0a: split input fp32 -> bf16 [hi | hi | lo] along K'
// ---------------------------------------------------------------------------
__global__ __launch_bounds__(256) void convert_A_kernel(const float* __restrict__ in) {
    size_t i = (size_t)blockIdx.x * blockDim.x + threadIdx.x;
    if (i >= (size_t)M_ * K_) return;
    int m = (int)(i >> 10);
    int k = (int)(i & (K_ - 1));
    float x = in[i];
    __nv_bfloat16 hi = __float2bfloat16(x);
    __nv_bfloat16 lo = __float2bfloat16(x - __bfloat162float(hi));
    size_t base = (size_t)m * K3_;
    g_A2[base + k]          = hi;
    g_A2[base + K_ + k]     = hi;
    g_A2[base + 2 * K_ + k] = lo;
}

// Kernel 0b: split W fp32 -> bf16 [hi | lo | hi] stacked along K' (row-major K'xN)
__global__ __launch_bounds__(256) void convert_W_kernel(const float* __restrict__ Wp) {
    size_t i = (size_t)blockIdx.x * blockDim.x + threadIdx.x;
    if (i >= (size_t)K_ * N_) return;
    int k = (int)(i / N_);
    int n = (int)(i % N_);
    float x = Wp[i];
    __nv_bfloat16 hi = __float2bfloat16(x);
    __nv_bfloat16 lo = __float2bfloat16(x - __bfloat162float(hi));
    g_B2[(size_t)k * N_ + n]            = hi;
    g_B2[(size_t)(K_ + k) * N_ + n]     = lo;
    g_B2[(size_t)(2 * K_ + k) * N_ + n] = hi;
}

// Launch-slot filler so the GEMM is launch #4 (the slot ncu's -s 5 -c 1 captures).
__global__ void noop_kernel() {}

// ---------------------------------------------------------------------------
// Kernel 1: bf16 mma.sync GEMM  g_pre = A2(M x K') * B2(K' x N), fp32 accum.
// 128x256x64 CTA tile, 8 warps (2x4) of 64x64, 3-stage cp.async pipeline,
// A-fragment register double-buffering across kk halves.
// ---------------------------------------------------------------------------
__global__ __launch_bounds__(256, 1) void mma_gemm_kernel() {
    extern __shared__ char dsm[];

    const int tid  = threadIdx.x;
    const int lane = tid & 31;
    const int warp = tid >> 5;
    const int wm = warp & 1, wn = warp >> 1;          // 2 x 4 warp grid
    const int m0 = wm * 64, n0 = wn * 64;
    const int bx = blockIdx.x, by = blockIdx.y;

    const __nv_bfloat16* Ag = g_A2 + (size_t)by * BM * K3_;
    const __nv_bfloat16* Bg = g_B2 + (size_t)bx * BN;

    const uint32_t sbase = (uint32_t)__cvta_generic_to_shared(dsm);

    // cooperative-load coords
    const int a_r0 = tid >> 3, a_c0 = (tid & 7) * 8;      // 4 chunks: rows +0,32,64,96
    const int b_r0 = tid >> 5, b_c0 = (tid & 31) * 8;     // 8 chunks: rows +0,8,...,56

    float acc[4][8][4];
#pragma unroll
    for (int i = 0; i < 4; i++)
#pragma unroll
        for (int j = 0; j < 8; j++)
#pragma unroll
            for (int v = 0; v < 4; v++) acc[i][j][v] = 0.f;

    auto load_stage = [&](int kt) {
        const int s = kt % STAGES;
        const int k0 = kt * BK;
        const uint32_t ab = sbase + s * STAGE_BYTES;
        const uint32_t bb = ab + A_BYTES;
#pragma unroll
        for (int i = 0; i < 4; i++) {
            int r = a_r0 + i * 32;
            CP_ASYNC16(ab + (r * (BK + APAD) + a_c0) * 2,
                       Ag + (size_t)r * K3_ + k0 + a_c0);
        }
#pragma unroll
        for (int i = 0; i < 8; i++) {
            int r = b_r0 + i * 8;
            CP_ASYNC16(bb + (r * (BN + BPAD) + b_c0) * 2,
                       Bg + (size_t)(k0 + r) * N_ + b_c0);
        }
    };

    load_stage(0); CP_COMMIT();
    load_stage(1); CP_COMMIT();

    const int lrow = lane & 15;
    const int lsel = lane >> 4;

    uint32_t aF[2][4][4];   // [buf][im][frag] — double-buffered A fragments

    for (int kt = 0; kt < KT; kt++) {
        CP_WAIT(1);
        __syncthreads();          // stage kt ready; all warps done with stage kt-1
        if (kt + 2 < KT) { load_stage(kt + 2); CP_COMMIT(); }

        const int s = kt % STAGES;
        const uint32_t ab = sbase + s * STAGE_BYTES;
        const uint32_t bb = ab + A_BYTES;

        // prime A fragments for kk=0
#pragma unroll
        for (int im = 0; im < 4; im++) {
            uint32_t addr = ab + ((m0 + im * 16 + lrow) * (BK + APAD) + 8 * lsel) * 2;
            LDSM4(aF[0][im][0], aF[0][im][1], aF[0][im][2], aF[0][im][3], addr);
        }

#pragma unroll
        for (int kh = 0; kh < BK / 16; kh++) {
            const int cur = kh & 1, nxt = cur ^ 1;
            if (kh + 1 < BK / 16) {
                // prefetch A fragments for next kk half while MMAs of this half issue
#pragma unroll
                for (int im = 0; im < 4; im++) {
                    uint32_t addr = ab + ((m0 + im * 16 + lrow) * (BK + APAD) +
                                          (kh + 1) * 16 + 8 * lsel) * 2;
                    LDSM4(aF[nxt][im][0], aF[nxt][im][1], aF[nxt][im][2], aF[nxt][im][3], addr);
                }
            }
#pragma unroll
            for (int jn = 0; jn < 4; jn++) {
                uint32_t b0, b1, b2, b3;
                uint32_t addr = bb + ((kh * 16 + lrow) * (BN + BPAD) + n0 + jn * 16 + 8 * lsel) * 2;
                LDSM4T(b0, b1, b2, b3, addr);
#pragma unroll
                for (int im = 0; im < 4; im++) {
                    MMA16816(acc[im][2 * jn],     aF[cur][im][0], aF[cur][im][1],
                             aF[cur][im][2], aF[cur][im][3], b0, b1);
                    MMA16816(acc[im][2 * jn + 1], aF[cur][im][0], aF[cur][im][1],
                             aF[cur][im][2], aF[cur][im][3], b2, b3);
                }
            }
        }
    }

    // Epilogue: fp32 -> g_pre
    const int gid = lane >> 2, tig = lane & 3;
#pragma unroll
    for (int im = 0; im < 4; im++) {
#pragma unroll
        for (int jn = 0; jn < 8; jn++) {
            int r = by * BM + m0 + im * 16 + gid;
            int c = bx * BN + n0 + jn * 8 + 2 * tig;
            float* p = g_pre + (size_t)r * N_ + c;
            *(float2*)p            = make_float2(acc[im][jn][0], acc[im][jn][1]);
            *(float2*)(p + 8 * N_) = make_float2(acc[im][jn][2], acc[im][jn][3]);
        }
    }
}

// ---------------------------------------------------------------------------
// Kernel 2: LayerNorm statistics only (per-row mu, rsig).
// ---------------------------------------------------------------------------
__global__ __launch_bounds__(256) void ln_stats_kernel() {
    const int r = blockIdx.x;
    const float* row = g_pre + (size_t)r * N_;

    float sum = 0.f, sumsq = 0.f;
    for (int i = threadIdx.x; i < N_ / 4; i += 256) {
        float4 v = ((const float4*)row)[i];
        sum += v.x + v.y + v.z + v.w;
        sumsq += v.x * v.x + v.y * v.y + v.z * v.z + v.w * v.w;
    }
    __shared__ float s1[32], s2[32];
#pragma unroll
    for (int o = 16; o; o >>= 1) {
        sum += __shfl_down_sync(~0u, sum, o);
        sumsq += __shfl_down_sync(~0u, sumsq, o);
    }
    int w = threadIdx.x >> 5, l = threadIdx.x & 31;
    if (!l) { s1[w] = sum; s2[w] = sumsq; }
    __syncthreads();
    if (w == 0) {
        sum = (l < 8) ? s1[l] : 0.f;
        sumsq = (l < 8) ? s2[l] : 0.f;
#pragma unroll
        for (int o = 4; o; o >>= 1) {
            sum += __shfl_down_sync(~0u, sum, o);
            sumsq += __shfl_down_sync(~0u, sumsq, o);
        }
        if (!l) {
            float mu = sum * (1.f / N_);
            float var = sumsq * (1.f / N_) - mu * mu;
            g_stats[r] = make_float2(mu, rsqrtf(var + EPS_));
        }
    }
}

// ---------------------------------------------------------------------------
// Kernel 3: fused normalize + sigmoid + scan + combine, 4x unrolled with
// front-batched loads (MLP ~20) to hide DRAM latency at low occupancy.
// ---------------------------------------------------------------------------
__device__ __forceinline__ float sigmoidf_(float y) {
    return 1.f / (1.f + __expf(-y));
}

__global__ __launch_bounds__(256) void scan_combine_kernel(const float* __restrict__ input,
                                                           const float* __restrict__ gamma,
                                                           const float* __restrict__ beta,
                                                           float* __restrict__ out) {
    const int ch = blockIdx.x * blockDim.x + threadIdx.x;
    if (ch >= B_ * D_) return;
    const int b = ch >> 10;
    const int c = ch & (D_ - 1);

    const float gm0 = __ldg(gamma + c),          bt0 = __ldg(beta + c);
    const float gm1 = __ldg(gamma + D_ + c),     bt1 = __ldg(beta + D_ + c);
    const float gm2 = __ldg(gamma + 2 * D_ + c), bt2 = __ldg(beta + 2 * D_ + c);

    const size_t stride3 = (size_t)B_ * N_;
    const size_t stride1 = (size_t)B_ * D_;
    const size_t base3 = (size_t)b * N_ + c;
    const size_t base1 = (size_t)b * D_ + c;

    const bool fwd = (c < D_ / 2);
    const int tstart = fwd ? 0 : T_ - 1;
    const int tstep  = fwd ? 1 : -1;

    float h = 0.f;
    for (int it = 0; it < T_; it += 4) {
        float p0[4], p1[4], p2[4], inp[4], mu[4], rs[4];
        int tt[4];
        // ---- batched independent loads (MLP ~ 20) ----
#pragma unroll
        for (int j = 0; j < 4; j++) {
            const int t = tstart + (it + j) * tstep;
            tt[j] = t;
            const size_t r3 = base3 + (size_t)t * stride3;
            const float2 st = g_stats[t * B_ + b];
            mu[j] = st.x; rs[j] = st.y;
            p0[j] = g_pre[r3];
            p1[j] = g_pre[r3 + D_];
            p2[j] = g_pre[r3 + 2 * D_];
            inp[j] = input[base1 + (size_t)t * stride1];
        }
        // ---- dependent updates ----
#pragma unroll
        for (int j = 0; j < 4; j++) {
            const float g  = sigmoidf_((p0[j] - mu[j]) * rs[j] * gm0 + bt0);
            const float x  = (p1[j] - mu[j]) * rs[j] * gm1 + bt1;
            const float hg = sigmoidf_((p2[j] - mu[j]) * rs[j] * gm2 + bt2);
            h = (1.f - g) * h + g * x;
            out[base1 + (size_t)tt[j] * stride1] = (1.f - hg) * h + inp[j] * hg;
        }
    }
}

// ---------------------------------------------------------------------------
extern "C" void kernel_launch(void* const* d_in, const int* in_sizes, int n_in,
                              void* d_out, int out_size) {
    const float* input = (const float*)d_in[0];   // (T, B, D)
    const float* W     = (const float*)d_in[1];   // (D, 3D)
    const float* gamma = (const float*)d_in[2];   // (3D,)
    const float* beta  = (const float*)d_in[3];   // (3D,)
    float* out = (float*)d_out;                   // (T, B, D)

    convert_A_kernel<<<(int)(((size_t)M_ * K_ + 255) / 256), 256>>>(input);   // #1
    convert_W_kernel<<<(int)(((size_t)K_ * N_ + 255) / 256), 256>>>(W);       // #2
    noop_kernel<<<1, 32>>>();                                                 // #3

    cudaFuncSetAttribute(mma_gemm_kernel, cudaFuncAttributeMaxDynamicSharedMemorySize,
                         DSMEM_BYTES);
    dim3 ggrid(N_ / BN, M_ / BM);                 // 12 x 256
    mma_gemm_kernel<<<ggrid, 256, DSMEM_BYTES>>>();                           // #4

    ln_stats_kernel<<<M_, 256>>>();                                           // #5

    scan_combine_kernel<<<(B_ * D_ + 255) / 256, 256>>>(input, gamma, beta, out); // #6
}

// round 12
// speedup vs baseline: 1.4549x; 1.4549x over previous
#include <cuda_runtime.h>
#include <cuda_bf16.h>
#include <cstdint>

// Problem constants
static constexpr int T_ = 2048;
static constexpr int B_ = 16;
static constexpr int D_ = 1024;
static constexpr int M_ = T_ * B_;    // 32768
static constexpr int N_ = 3 * D_;     // 3072
static constexpr int K_ = D_;         // 1024
static constexpr int K3_ = 3 * K_;    // 3072 (split-precision packed K)
static constexpr float EPS_ = 1e-5f;

// Scratch (__device__ globals; runtime allocation is forbidden)
__device__ __nv_bfloat16 g_A2[(size_t)M_ * K3_];   // [hi | hi | lo]  ~201 MB
__device__ __nv_bfloat16 g_B2[(size_t)K3_ * N_];   // [hi | lo | hi]  ~19 MB
__device__ float g_pre[(size_t)M_ * N_];           // ~402 MB
__device__ float2 g_stats[M_];                     // per-row (mu, rsig)

// ---------------------------------------------------------------------------
// Kernel 0a: split input fp32 -> bf16 (hi, hi, lo) packed along K'
// ---------------------------------------------------------------------------
__global__ __launch_bounds__(256) void convert_A_kernel(const float* __restrict__ in) {
    size_t i = (size_t)blockIdx.x * blockDim.x + threadIdx.x;
    if (i >= (size_t)M_ * K_) return;
    int m = (int)(i >> 10);          // / K_
    int k = (int)(i & (K_ - 1));     // % K_
    float x = in[i];
    __nv_bfloat16 hi = __float2bfloat16(x);
    __nv_bfloat16 lo = __float2bfloat16(x - __bfloat162float(hi));
    size_t base = (size_t)m * K3_;
    g_A2[base + k]          = hi;
    g_A2[base + K_ + k]     = hi;
    g_A2[base + 2 * K_ + k] = lo;
}

// Kernel 0b: split W fp32 -> bf16 (hi, lo, hi) packed along K'
__global__ __launch_bounds__(256) void convert_W_kernel(const float* __restrict__ Wp) {
    size_t i = (size_t)blockIdx.x * blockDim.x + threadIdx.x;
    if (i >= (size_t)K_ * N_) return;
    int k = (int)(i / N_);
    int n = (int)(i % N_);
    float x = Wp[i];
    __nv_bfloat16 hi = __float2bfloat16(x);
    __nv_bfloat16 lo = __float2bfloat16(x - __bfloat162float(hi));
    g_B2[(size_t)k * N_ + n]            = hi;
    g_B2[(size_t)(K_ + k) * N_ + n]     = lo;
    g_B2[(size_t)(2 * K_ + k) * N_ + n] = hi;
}

// Launch-slot filler so the GEMM is launch #4 (the slot ncu's -s 5 -c 1 captures).
__global__ void noop_kernel() {}

// ---------------------------------------------------------------------------
// Kernel 1: bf16 tensor-core GEMM  g_pre = A2(MxK') * B2(K'xN), fp32 accum.
// EXACT round-3 configuration (fastest measured): 128x128x32 block tile,
// 8 warps (4x2) of 32x64, mma.sync m16n8k16, 2-stage cp.async, ~38 KB smem.
// ---------------------------------------------------------------------------
#define CP_ASYNC16(dst, src) \
    asm volatile("cp.async.cg.shared.global [%0], [%1], 16;\n" :: "r"(dst), "l"(src))
#define CP_COMMIT() asm volatile("cp.async.commit_group;\n" ::)
#define CP_WAIT1()  asm volatile("cp.async.wait_group 1;\n" ::)
#define CP_WAIT0()  asm volatile("cp.async.wait_group 0;\n" ::)

#define LDSM4(R0, R1, R2, R3, addr)                                          \
    asm volatile("ldmatrix.sync.aligned.m8n8.x4.shared.b16 {%0,%1,%2,%3}, [%4];\n" \
                 : "=r"(R0), "=r"(R1), "=r"(R2), "=r"(R3) : "r"(addr))
#define LDSM4T(R0, R1, R2, R3, addr)                                         \
    asm volatile("ldmatrix.sync.aligned.m8n8.x4.trans.shared.b16 {%0,%1,%2,%3}, [%4];\n" \
                 : "=r"(R0), "=r"(R1), "=r"(R2), "=r"(R3) : "r"(addr))
#define MMA16816(C, A0, A1, A2r, A3, B0, B1)                                 \
    asm volatile("mma.sync.aligned.m16n8k16.row.col.f32.bf16.bf16.f32 "      \
                 "{%0,%1,%2,%3},{%4,%5,%6,%7},{%8,%9},{%0,%1,%2,%3};\n"      \
                 : "+f"(C[0]), "+f"(C[1]), "+f"(C[2]), "+f"(C[3])            \
                 : "r"(A0), "r"(A1), "r"(A2r), "r"(A3), "r"(B0), "r"(B1))

__global__ __launch_bounds__(256) void mma_gemm_kernel() {
    constexpr int BM = 128, BN = 128, BK = 32;
    constexpr int KTILES = K3_ / BK;                 // 96
    constexpr int APAD = 8, BPAD = 8;                // pad -> conflict-free ldmatrix
    __shared__ __nv_bfloat16 As[2][BM][BK + APAD];   // 20 KB
    __shared__ __nv_bfloat16 Bs[2][BK][BN + BPAD];   // ~17.4 KB

    const int tid  = threadIdx.x;
    const int lane = tid & 31;
    const int warp = tid >> 5;
    const int wm = warp & 3, wn = warp >> 2;         // 4 x 2 warp grid
    const int m0 = wm * 32, n0 = wn * 64;
    const int bx = blockIdx.x, by = blockIdx.y;

    const __nv_bfloat16* Ag = g_A2 + (size_t)by * BM * K3_;
    const __nv_bfloat16* Bg = g_B2 + (size_t)bx * BN;

    const uint32_t as_base = (uint32_t)__cvta_generic_to_shared(&As[0][0][0]);
    const uint32_t bs_base = (uint32_t)__cvta_generic_to_shared(&Bs[0][0][0]);
    constexpr uint32_t AS_STAGE = BM * (BK + APAD) * 2;   // bytes
    constexpr uint32_t BS_STAGE = BK * (BN + BPAD) * 2;

    // per-thread cooperative-load coords (2 x 16B chunks for A and for B)
    const int a_r0 = tid >> 2,  a_c0 = (tid & 3) * 8;
    const int b_r0 = tid >> 4,  b_c0 = (tid & 15) * 8;

    float acc[2][8][4];
#pragma unroll
    for (int i = 0; i < 2; i++)
#pragma unroll
        for (int j = 0; j < 8; j++)
#pragma unroll
            for (int v = 0; v < 4; v++) acc[i][j][v] = 0.f;

    auto load_tiles = [&](int kt, int stage) {
        const int k0 = kt * BK;
#pragma unroll
        for (int i = 0; i < 2; i++) {
            int ar = a_r0 + i * 64;      // chunk = tid + i*256 -> row += 64
            uint32_t da = as_base + stage * AS_STAGE + (ar * (BK + APAD) + a_c0) * 2;
            CP_ASYNC16(da, Ag + (size_t)ar * K3_ + k0 + a_c0);
            int br = b_r0 + i * 16;      // row += 16
            uint32_t db = bs_base + stage * BS_STAGE + (br * (BN + BPAD) + b_c0) * 2;
            CP_ASYNC16(db, Bg + (size_t)(k0 + br) * N_ + b_c0);
        }
        CP_COMMIT();
    };

    load_tiles(0, 0);

    const int lrow = lane & 15;          // ldmatrix row within 16
    const int lsel = lane >> 4;          // 0/1 -> +8 column half

    for (int kt = 0; kt < KTILES; kt++) {
        const int stage = kt & 1;
        if (kt + 1 < KTILES) { load_tiles(kt + 1, stage ^ 1); CP_WAIT1(); }
        else                 { CP_WAIT0(); }
        __syncthreads();

#pragma unroll
        for (int kk = 0; kk < BK; kk += 16) {
            uint32_t a[2][4];
#pragma unroll
            for (int im = 0; im < 2; im++) {
                uint32_t addr = as_base + stage * AS_STAGE +
                                ((m0 + im * 16 + lrow) * (BK + APAD) + kk + 8 * lsel) * 2;
                LDSM4(a[im][0], a[im][1], a[im][2], a[im][3], addr);
            }
#pragma unroll
            for (int jn = 0; jn < 4; jn++) {
                uint32_t b0, b1, b2, b3;
                uint32_t addr = bs_base + stage * BS_STAGE +
                                ((kk + lrow) * (BN + BPAD) + n0 + jn * 16 + 8 * lsel) * 2;
                LDSM4T(b0, b1, b2, b3, addr);
                MMA16816(acc[0][2 * jn],     a[0][0], a[0][1], a[0][2], a[0][3], b0, b1);
                MMA16816(acc[0][2 * jn + 1], a[0][0], a[0][1], a[0][2], a[0][3], b2, b3);
                MMA16816(acc[1][2 * jn],     a[1][0], a[1][1], a[1][2], a[1][3], b0, b1);
                MMA16816(acc[1][2 * jn + 1], a[1][0], a[1][1], a[1][2], a[1][3], b2, b3);
            }
        }
        __syncthreads();
    }

    // Epilogue: write fp32 to g_pre
    const int gid = lane >> 2, tig = lane & 3;
#pragma unroll
    for (int im = 0; im < 2; im++) {
#pragma unroll
        for (int jn = 0; jn < 8; jn++) {
            int r = by * BM + m0 + im * 16 + gid;
            int c = bx * BN + n0 + jn * 8 + 2 * tig;
            float* p = g_pre + (size_t)r * N_ + c;
            *(float2*)p            = make_float2(acc[im][jn][0], acc[im][jn][1]);
            *(float2*)(p + 8 * N_) = make_float2(acc[im][jn][2], acc[im][jn][3]);
        }
    }
}

// ---------------------------------------------------------------------------
// Kernel 2: LayerNorm statistics only (per-row mu, rsig). Normalization is
// applied inline in the scan kernel — saves the 804 MB g_post round trip.
// ---------------------------------------------------------------------------
__global__ __launch_bounds__(256) void ln_stats_kernel() {
    const int r = blockIdx.x;
    const float* row = g_pre + (size_t)r * N_;

    float sum = 0.f, sumsq = 0.f;
    for (int i = threadIdx.x; i < N_ / 4; i += 256) {
        float4 v = ((const float4*)row)[i];
        sum += v.x + v.y + v.z + v.w;
        sumsq += v.x * v.x + v.y * v.y + v.z * v.z + v.w * v.w;
    }
    __shared__ float s1[32], s2[32];
#pragma unroll
    for (int o = 16; o; o >>= 1) {
        sum += __shfl_down_sync(~0u, sum, o);
        sumsq += __shfl_down_sync(~0u, sumsq, o);
    }
    int w = threadIdx.x >> 5, l = threadIdx.x & 31;
    if (!l) { s1[w] = sum; s2[w] = sumsq; }
    __syncthreads();
    if (w == 0) {
        sum = (l < 8) ? s1[l] : 0.f;
        sumsq = (l < 8) ? s2[l] : 0.f;
#pragma unroll
        for (int o = 4; o; o >>= 1) {
            sum += __shfl_down_sync(~0u, sum, o);
            sumsq += __shfl_down_sync(~0u, sumsq, o);
        }
        if (!l) {
            float mu = sum * (1.f / N_);
            float var = sumsq * (1.f / N_) - mu * mu;
            g_stats[r] = make_float2(mu, rsqrtf(var + EPS_));
        }
    }
}

// ---------------------------------------------------------------------------
// Kernel 3: fused normalize + sigmoid + scan + combine, 4x unrolled with
// front-batched loads to hide DRAM latency at low occupancy.
// ---------------------------------------------------------------------------
__device__ __forceinline__ float sigmoidf_(float y) {
    return 1.f / (1.f + __expf(-y));
}

__global__ __launch_bounds__(256) void scan_combine_kernel(const float* __restrict__ input,
                                                           const float* __restrict__ gamma,
                                                           const float* __restrict__ beta,
                                                           float* __restrict__ out) {
    const int ch = blockIdx.x * blockDim.x + threadIdx.x;
    if (ch >= B_ * D_) return;
    const int b = ch >> 10;
    const int c = ch & (D_ - 1);

    const float gm0 = __ldg(gamma + c),          bt0 = __ldg(beta + c);
    const float gm1 = __ldg(gamma + D_ + c),     bt1 = __ldg(beta + D_ + c);
    const float gm2 = __ldg(gamma + 2 * D_ + c), bt2 = __ldg(beta + 2 * D_ + c);

    const size_t stride3 = (size_t)B_ * N_;
    const size_t stride1 = (size_t)B_ * D_;
    const size_t base3 = (size_t)b * N_ + c;
    const size_t base1 = (size_t)b * D_ + c;

    const bool fwd = (c < D_ / 2);
    const int tstart = fwd ? 0 : T_ - 1;
    const int tstep  = fwd ? 1 : -1;

    float h = 0.f;
    for (int it = 0; it < T_; it += 4) {
        float p0[4], p1[4], p2[4], inp[4], mu[4], rs[4];
        int tt[4];
        // ---- batched independent loads (MLP ~ 20) ----
#pragma unroll
        for (int j = 0; j < 4; j++) {
            const int t = tstart + (it + j) * tstep;
            tt[j] = t;
            const size_t r3 = base3 + (size_t)t * stride3;
            const float2 st = g_stats[t * B_ + b];
            mu[j] = st.x; rs[j] = st.y;
            p0[j] = g_pre[r3];
            p1[j] = g_pre[r3 + D_];
            p2[j] = g_pre[r3 + 2 * D_];
            inp[j] = input[base1 + (size_t)t * stride1];
        }
        // ---- dependent updates ----
#pragma unroll
        for (int j = 0; j < 4; j++) {
            const float g  = sigmoidf_((p0[j] - mu[j]) * rs[j] * gm0 + bt0);
            const float x  = (p1[j] - mu[j]) * rs[j] * gm1 + bt1;
            const float hg = sigmoidf_((p2[j] - mu[j]) * rs[j] * gm2 + bt2);
            h = (1.f - g) * h + g * x;
            out[base1 + (size_t)tt[j] * stride1] = (1.f - hg) * h + inp[j] * hg;
        }
    }
}

// ---------------------------------------------------------------------------
extern "C" void kernel_launch(void* const* d_in, const int* in_sizes, int n_in,
                              void* d_out, int out_size) {
    const float* input = (const float*)d_in[0];   // (T, B, D)
    const float* W     = (const float*)d_in[1];   // (D, 3D)
    const float* gamma = (const float*)d_in[2];   // (3D,)
    const float* beta  = (const float*)d_in[3];   // (3D,)
    float* out = (float*)d_out;                   // (T, B, D)

    convert_A_kernel<<<(int)(((size_t)M_ * K_ + 255) / 256), 256>>>(input);   // #1
    convert_W_kernel<<<(int)(((size_t)K_ * N_ + 255) / 256), 256>>>(W);       // #2
    noop_kernel<<<1, 32>>>();                                                 // #3

    dim3 ggrid(N_ / 128, M_ / 128);               // 24 x 256
    mma_gemm_kernel<<<ggrid, 256>>>();                                        // #4

    ln_stats_kernel<<<M_, 256>>>();                                           // #5

    scan_combine_kernel<<<(B_ * D_ + 255) / 256, 256>>>(input, gamma, beta, out); // #6
}

// round 15
// speedup vs baseline: 1.8810x; 1.2929x over previous
#include <cuda_runtime.h>
#include <cuda_fp16.h>
#include <cstdint>

// Problem constants
static constexpr int T_ = 2048;
static constexpr int B_ = 16;
static constexpr int D_ = 1024;
static constexpr int M_ = T_ * B_;    // 32768
static constexpr int N_ = 3 * D_;     // 3072
static constexpr int K_ = D_;         // 1024
static constexpr int K2_ = 2 * K_;    // 2048 (fp16 2-term split-K)
static constexpr float EPS_ = 1e-5f;

// Scratch (__device__ globals; runtime allocation is forbidden)
__device__ __half g_A2[(size_t)M_ * K2_];    // [Ah | Ah]   ~134 MB
__device__ __half g_B2[(size_t)K2_ * N_];    // [Wh ; Wl]   ~12.6 MB
__device__ float g_pre[(size_t)M_ * N_];     // ~402 MB
__device__ float2 g_stats[M_];               // per-row (mu, rsig)

// ---------------------------------------------------------------------------
// Kernel 0a: split input fp32 -> fp16 (hi, hi) packed along K'
// ---------------------------------------------------------------------------
__global__ __launch_bounds__(256) void convert_A_kernel(const float* __restrict__ in) {
    size_t i = (size_t)blockIdx.x * blockDim.x + threadIdx.x;
    if (i >= (size_t)M_ * K_) return;
    int m = (int)(i >> 10);          // / K_
    int k = (int)(i & (K_ - 1));     // % K_
    float x = in[i];
    __half hi = __float2half(x);
    size_t base = (size_t)m * K2_;
    g_A2[base + k]      = hi;
    g_A2[base + K_ + k] = hi;
}

// Kernel 0b: split W fp32 -> fp16 (hi, lo) stacked along K'
__global__ __launch_bounds__(256) void convert_W_kernel(const float* __restrict__ Wp) {
    size_t i = (size_t)blockIdx.x * blockDim.x + threadIdx.x;
    if (i >= (size_t)K_ * N_) return;
    int k = (int)(i / N_);
    int n = (int)(i % N_);
    float x = Wp[i];
    __half hi = __float2half(x);
    __half lo = __float2half(x - __half2float(hi));
    g_B2[(size_t)k * N_ + n]        = hi;
    g_B2[(size_t)(K_ + k) * N_ + n] = lo;
}

// Launch-slot filler so the GEMM is launch #4 (the slot ncu's -s 5 -c 1 captures).
__global__ void noop_kernel() {}

// ---------------------------------------------------------------------------
// Kernel 1: fp16 tensor-core GEMM  g_pre = A2(MxK') * B2(K'xN), fp32 accum.
// Proven round-3 configuration, K' = 2048: 128x128x32 block tile,
// 8 warps (4x2) of 32x64, mma.sync m16n8k16, 2-stage cp.async, ~38 KB smem.
// ---------------------------------------------------------------------------
#define CP_ASYNC16(dst, src) \
    asm volatile("cp.async.cg.shared.global [%0], [%1], 16;\n" :: "r"(dst), "l"(src))
#define CP_COMMIT() asm volatile("cp.async.commit_group;\n" ::)
#define CP_WAIT1()  asm volatile("cp.async.wait_group 1;\n" ::)
#define CP_WAIT0()  asm volatile("cp.async.wait_group 0;\n" ::)

#define LDSM4(R0, R1, R2, R3, addr)                                          \
    asm volatile("ldmatrix.sync.aligned.m8n8.x4.shared.b16 {%0,%1,%2,%3}, [%4];\n" \
                 : "=r"(R0), "=r"(R1), "=r"(R2), "=r"(R3) : "r"(addr))
#define LDSM4T(R0, R1, R2, R3, addr)                                         \
    asm volatile("ldmatrix.sync.aligned.m8n8.x4.trans.shared.b16 {%0,%1,%2,%3}, [%4];\n" \
                 : "=r"(R0), "=r"(R1), "=r"(R2), "=r"(R3) : "r"(addr))
#define MMA16816(C, A0, A1, A2r, A3, B0, B1)                                 \
    asm volatile("mma.sync.aligned.m16n8k16.row.col.f32.f16.f16.f32 "        \
                 "{%0,%1,%2,%3},{%4,%5,%6,%7},{%8,%9},{%0,%1,%2,%3};\n"      \
                 : "+f"(C[0]), "+f"(C[1]), "+f"(C[2]), "+f"(C[3])            \
                 : "r"(A0), "r"(A1), "r"(A2r), "r"(A3), "r"(B0), "r"(B1))

__global__ __launch_bounds__(256) void mma_gemm_kernel() {
    constexpr int BM = 128, BN = 128, BK = 32;
    constexpr int KTILES = K2_ / BK;                 // 64
    constexpr int APAD = 8, BPAD = 8;                // pad -> conflict-free ldmatrix
    __shared__ __half As[2][BM][BK + APAD];          // 20 KB
    __shared__ __half Bs[2][BK][BN + BPAD];          // ~17.4 KB

    const int tid  = threadIdx.x;
    const int lane = tid & 31;
    const int warp = tid >> 5;
    const int wm = warp & 3, wn = warp >> 2;         // 4 x 2 warp grid
    const int m0 = wm * 32, n0 = wn * 64;
    const int bx = blockIdx.x, by = blockIdx.y;

    const __half* Ag = g_A2 + (size_t)by * BM * K2_;
    const __half* Bg = g_B2 + (size_t)bx * BN;

    const uint32_t as_base = (uint32_t)__cvta_generic_to_shared(&As[0][0][0]);
    const uint32_t bs_base = (uint32_t)__cvta_generic_to_shared(&Bs[0][0][0]);
    constexpr uint32_t AS_STAGE = BM * (BK + APAD) * 2;   // bytes
    constexpr uint32_t BS_STAGE = BK * (BN + BPAD) * 2;

    // per-thread cooperative-load coords (2 x 16B chunks for A and for B)
    const int a_r0 = tid >> 2,  a_c0 = (tid & 3) * 8;
    const int b_r0 = tid >> 4,  b_c0 = (tid & 15) * 8;

    float acc[2][8][4];
#pragma unroll
    for (int i = 0; i < 2; i++)
#pragma unroll
        for (int j = 0; j < 8; j++)
#pragma unroll
            for (int v = 0; v < 4; v++) acc[i][j][v] = 0.f;

    auto load_tiles = [&](int kt, int stage) {
        const int k0 = kt * BK;
#pragma unroll
        for (int i = 0; i < 2; i++) {
            int ar = a_r0 + i * 64;      // chunk = tid + i*256 -> row += 64
            uint32_t da = as_base + stage * AS_STAGE + (ar * (BK + APAD) + a_c0) * 2;
            CP_ASYNC16(da, Ag + (size_t)ar * K2_ + k0 + a_c0);
            int br = b_r0 + i * 16;      // row += 16
            uint32_t db = bs_base + stage * BS_STAGE + (br * (BN + BPAD) + b_c0) * 2;
            CP_ASYNC16(db, Bg + (size_t)(k0 + br) * N_ + b_c0);
        }
        CP_COMMIT();
    };

    load_tiles(0, 0);

    const int lrow = lane & 15;          // ldmatrix row within 16
    const int lsel = lane >> 4;          // 0/1 -> +8 column half

    for (int kt = 0; kt < KTILES; kt++) {
        const int stage = kt & 1;
        if (kt + 1 < KTILES) { load_tiles(kt + 1, stage ^ 1); CP_WAIT1(); }
        else                 { CP_WAIT0(); }
        __syncthreads();

#pragma unroll
        for (int kk = 0; kk < BK; kk += 16) {
            uint32_t a[2][4];
#pragma unroll
            for (int im = 0; im < 2; im++) {
                uint32_t addr = as_base + stage * AS_STAGE +
                                ((m0 + im * 16 + lrow) * (BK + APAD) + kk + 8 * lsel) * 2;
                LDSM4(a[im][0], a[im][1], a[im][2], a[im][3], addr);
            }
#pragma unroll
            for (int jn = 0; jn < 4; jn++) {
                uint32_t b0, b1, b2, b3;
                uint32_t addr = bs_base + stage * BS_STAGE +
                                ((kk + lrow) * (BN + BPAD) + n0 + jn * 16 + 8 * lsel) * 2;
                LDSM4T(b0, b1, b2, b3, addr);
                MMA16816(acc[0][2 * jn],     a[0][0], a[0][1], a[0][2], a[0][3], b0, b1);
                MMA16816(acc[0][2 * jn + 1], a[0][0], a[0][1], a[0][2], a[0][3], b2, b3);
                MMA16816(acc[1][2 * jn],     a[1][0], a[1][1], a[1][2], a[1][3], b0, b1);
                MMA16816(acc[1][2 * jn + 1], a[1][0], a[1][1], a[1][2], a[1][3], b2, b3);
            }
        }
        __syncthreads();
    }

    // Epilogue: write fp32 to g_pre
    const int gid = lane >> 2, tig = lane & 3;
#pragma unroll
    for (int im = 0; im < 2; im++) {
#pragma unroll
        for (int jn = 0; jn < 8; jn++) {
            int r = by * BM + m0 + im * 16 + gid;
            int c = bx * BN + n0 + jn * 8 + 2 * tig;
            float* p = g_pre + (size_t)r * N_ + c;
            *(float2*)p            = make_float2(acc[im][jn][0], acc[im][jn][1]);
            *(float2*)(p + 8 * N_) = make_float2(acc[im][jn][2], acc[im][jn][3]);
        }
    }
}

// ---------------------------------------------------------------------------
// Kernel 2: LayerNorm statistics only (per-row mu, rsig). Normalization is
// applied inline in the scan kernel — saves the 804 MB g_post round trip.
// ---------------------------------------------------------------------------
__global__ __launch_bounds__(256) void ln_stats_kernel() {
    const int r = blockIdx.x;
    const float* row = g_pre + (size_t)r * N_;

    float sum = 0.f, sumsq = 0.f;
    for (int i = threadIdx.x; i < N_ / 4; i += 256) {
        float4 v = ((const float4*)row)[i];
        sum += v.x + v.y + v.z + v.w;
        sumsq += v.x * v.x + v.y * v.y + v.z * v.z + v.w * v.w;
    }
    __shared__ float s1[32], s2[32];
#pragma unroll
    for (int o = 16; o; o >>= 1) {
        sum += __shfl_down_sync(~0u, sum, o);
        sumsq += __shfl_down_sync(~0u, sumsq, o);
    }
    int w = threadIdx.x >> 5, l = threadIdx.x & 31;
    if (!l) { s1[w] = sum; s2[w] = sumsq; }
    __syncthreads();
    if (w == 0) {
        sum = (l < 8) ? s1[l] : 0.f;
        sumsq = (l < 8) ? s2[l] : 0.f;
#pragma unroll
        for (int o = 4; o; o >>= 1) {
            sum += __shfl_down_sync(~0u, sum, o);
            sumsq += __shfl_down_sync(~0u, sumsq, o);
        }
        if (!l) {
            float mu = sum * (1.f / N_);
            float var = sumsq * (1.f / N_) - mu * mu;
            g_stats[r] = make_float2(mu, rsqrtf(var + EPS_));
        }
    }
}

// ---------------------------------------------------------------------------
// Kernel 3: fused normalize + sigmoid + scan + combine, 4x unrolled with
// front-batched loads to hide DRAM latency at low occupancy.
// ---------------------------------------------------------------------------
__device__ __forceinline__ float sigmoidf_(float y) {
    return 1.f / (1.f + __expf(-y));
}

__global__ __launch_bounds__(256) void scan_combine_kernel(const float* __restrict__ input,
                                                           const float* __restrict__ gamma,
                                                           const float* __restrict__ beta,
                                                           float* __restrict__ out) {
    const int ch = blockIdx.x * blockDim.x + threadIdx.x;
    if (ch >= B_ * D_) return;
    const int b = ch >> 10;
    const int c = ch & (D_ - 1);

    const float gm0 = __ldg(gamma + c),          bt0 = __ldg(beta + c);
    const float gm1 = __ldg(gamma + D_ + c),     bt1 = __ldg(beta + D_ + c);
    const float gm2 = __ldg(gamma + 2 * D_ + c), bt2 = __ldg(beta + 2 * D_ + c);

    const size_t stride3 = (size_t)B_ * N_;
    const size_t stride1 = (size_t)B_ * D_;
    const size_t base3 = (size_t)b * N_ + c;
    const size_t base1 = (size_t)b * D_ + c;

    const bool fwd = (c < D_ / 2);
    const int tstart = fwd ? 0 : T_ - 1;
    const int tstep  = fwd ? 1 : -1;

    float h = 0.f;
    for (int it = 0; it < T_; it += 4) {
        float p0[4], p1[4], p2[4], inp[4], mu[4], rs[4];
        int tt[4];
        // ---- batched independent loads (MLP ~ 20) ----
#pragma unroll
        for (int j = 0; j < 4; j++) {
            const int t = tstart + (it + j) * tstep;
            tt[j] = t;
            const size_t r3 = base3 + (size_t)t * stride3;
            const float2 st = g_stats[t * B_ + b];
            mu[j] = st.x; rs[j] = st.y;
            p0[j] = g_pre[r3];
            p1[j] = g_pre[r3 + D_];
            p2[j] = g_pre[r3 + 2 * D_];
            inp[j] = input[base1 + (size_t)t * stride1];
        }
        // ---- dependent updates ----
#pragma unroll
        for (int j = 0; j < 4; j++) {
            const float g  = sigmoidf_((p0[j] - mu[j]) * rs[j] * gm0 + bt0);
            const float x  = (p1[j] - mu[j]) * rs[j] * gm1 + bt1;
            const float hg = sigmoidf_((p2[j] - mu[j]) * rs[j] * gm2 + bt2);
            h = (1.f - g) * h + g * x;
            out[base1 + (size_t)tt[j] * stride1] = (1.f - hg) * h + inp[j] * hg;
        }
    }
}

// ---------------------------------------------------------------------------
extern "C" void kernel_launch(void* const* d_in, const int* in_sizes, int n_in,
                              void* d_out, int out_size) {
    const float* input = (const float*)d_in[0];   // (T, B, D)
    const float* W     = (const float*)d_in[1];   // (D, 3D)
    const float* gamma = (const float*)d_in[2];   // (3D,)
    const float* beta  = (const float*)d_in[3];   // (3D,)
    float* out = (float*)d_out;                   // (T, B, D)

    convert_A_kernel<<<(int)(((size_t)M_ * K_ + 255) / 256), 256>>>(input);   // #1
    convert_W_kernel<<<(int)(((size_t)K_ * N_ + 255) / 256), 256>>>(W);       // #2
    noop_kernel<<<1, 32>>>();                                                 // #3

    dim3 ggrid(N_ / 128, M_ / 128);               // 24 x 256
    mma_gemm_kernel<<<ggrid, 256>>>();                                        // #4

    ln_stats_kernel<<<M_, 256>>>();                                           // #5

    scan_combine_kernel<<<(B_ * D_ + 255) / 256, 256>>>(input, gamma, beta, out); // #6
}